// round 1
// baseline (speedup 1.0000x reference)
#include <cuda_runtime.h>

// Shapes (fixed by the problem)
#define Bq 2
#define Nq 2048
#define Mq 32
#define Hq 8
#define Dq 64
#define Eq 512
#define Fq 512
#define Pq 6

// Scratch: Q and K projections (graph-capture rules forbid cudaMalloc)
__device__ float g_Q[Bq * Nq * Eq];
__device__ float g_K[Bq * Nq * Eq];

// ---------------------------------------------------------------------------
// GEMM: C[4096,512] = X[4096,512] @ W[512,512], fp32.
// 128x128 block tile, TK=8, 256 threads, 8x8 register microtile.
// gridDim.z selects (query,Wq)->g_Q vs (key,Wk)->g_K.
// ---------------------------------------------------------------------------
__global__ __launch_bounds__(256) void gemm_qk_kernel(
    const float* __restrict__ Xq, const float* __restrict__ Wq_,
    const float* __restrict__ Xk, const float* __restrict__ Wk_)
{
    const float* X = blockIdx.z ? Xk : Xq;
    const float* W = blockIdx.z ? Wk_ : Wq_;
    float*       C = blockIdx.z ? g_K : g_Q;

    __shared__ float As[8][128];   // As[k][row]
    __shared__ float Bs[8][128];   // Bs[k][col]

    const int tid = threadIdx.x;
    const int ty = tid >> 4;          // 0..15
    const int tx = tid & 15;          // 0..15
    const int rowBase = blockIdx.y * 128;
    const int colBase = blockIdx.x * 128;

    // global->smem load assignment
    const int arow = tid >> 1;            // 0..127
    const int akc  = (tid & 1) * 4;       // 0 or 4
    const int brow = tid >> 5;            // 0..7
    const int bcol = (tid & 31) * 4;      // 0..124

    float acc[8][8];
#pragma unroll
    for (int i = 0; i < 8; i++)
#pragma unroll
        for (int j = 0; j < 8; j++) acc[i][j] = 0.f;

    for (int kt = 0; kt < Fq; kt += 8) {
        // Load next tiles into registers (no smem touched yet)
        float4 a4 = *(const float4*)(X + (size_t)(rowBase + arow) * Fq + kt + akc);
        float4 b4 = *(const float4*)(W + (size_t)(kt + brow) * Eq + colBase + bcol);

        __syncthreads();  // previous compute done -> safe to overwrite smem

        As[akc + 0][arow] = a4.x;
        As[akc + 1][arow] = a4.y;
        As[akc + 2][arow] = a4.z;
        As[akc + 3][arow] = a4.w;
        *(float4*)&Bs[brow][bcol] = b4;

        __syncthreads();

#pragma unroll
        for (int k = 0; k < 8; k++) {
            float4 a0 = *(const float4*)&As[k][ty * 8];
            float4 a1 = *(const float4*)&As[k][ty * 8 + 4];
            float4 b0 = *(const float4*)&Bs[k][tx * 8];
            float4 b1 = *(const float4*)&Bs[k][tx * 8 + 4];
            float a[8] = {a0.x, a0.y, a0.z, a0.w, a1.x, a1.y, a1.z, a1.w};
            float b[8] = {b0.x, b0.y, b0.z, b0.w, b1.x, b1.y, b1.z, b1.w};
#pragma unroll
            for (int i = 0; i < 8; i++)
#pragma unroll
                for (int j = 0; j < 8; j++)
                    acc[i][j] = fmaf(a[i], b[j], acc[i][j]);
        }
    }

    float* Cp = C + (size_t)(rowBase + ty * 8) * Eq + colBase + tx * 8;
#pragma unroll
    for (int i = 0; i < 8; i++) {
        float4 o0 = make_float4(acc[i][0], acc[i][1], acc[i][2], acc[i][3]);
        float4 o1 = make_float4(acc[i][4], acc[i][5], acc[i][6], acc[i][7]);
        *(float4*)(Cp + (size_t)i * Eq)     = o0;
        *(float4*)(Cp + (size_t)i * Eq + 4) = o1;
    }
}

// ---------------------------------------------------------------------------
// Fused epilogue: one CTA (256 thr, 8 warps) per token (b,n).
//   proj[p,h]  = sum_d Wl[p, h*64+d] * (Q[b,n]+v)[h*64+d]   (warps 0..5)
//   kb[h]      = sum_d K[b,n, h*64+d] * u[h*64+d]           (warp 6)
//   cont[m,h]  = sum_d Q[b,n, h*64+d] * K[b,nbhd, h*64+d]   (all warps, 4 m each)
//   A[b,n,m,h] = (cont + sum_p pl[b,n,m,p]*proj[p,h] + kb[h]) / 8
// Lane layout: lane l owns elements [l*16, l*16+16) -> head h = l/4; reduce
// over the 4-lane group with shfl_xor(1), shfl_xor(2).
// ---------------------------------------------------------------------------
__global__ __launch_bounds__(256) void fuse_kernel(
    const float* __restrict__ pl,     // (B,N,M,P)
    const int*   __restrict__ nbhd,   // (B,N,M)
    const float* __restrict__ Wl,     // (P,E)
    const float* __restrict__ u,      // (H,1,D) = 512 contiguous
    const float* __restrict__ v,      // (H,1,D) = 512 contiguous
    float*       __restrict__ out)    // (B,N,M,H)
{
    const int bn = blockIdx.x;        // 0..4095
    const int b  = bn / Nq;

    __shared__ float Qrow[Eq];
    __shared__ float Qvrow[Eq];
    __shared__ float Krow[Eq];
    __shared__ float proj[Pq][Hq];
    __shared__ float kb[Hq];
    __shared__ float cont[Mq][Hq];

    const int tid = threadIdx.x;
    const float* Qg = g_Q + (size_t)bn * Eq;
    const float* Kg = g_K + (size_t)bn * Eq;

    for (int i = tid; i < Eq; i += 256) {
        float q = Qg[i];
        Qrow[i]  = q;
        Qvrow[i] = q + v[i];
        Krow[i]  = Kg[i];
    }
    __syncthreads();

    const int w = tid >> 5;
    const int l = tid & 31;
    const int base = l * 16;

    // proj (warps 0..5) / key_bias (warp 6)
    if (w < 7) {
        const float* Avec = (w < 6) ? (Wl + w * Eq) : u;
        const float* Xvec = (w < 6) ? Qvrow : Krow;
        float s = 0.f;
#pragma unroll
        for (int i = 0; i < 16; i++) s = fmaf(Avec[base + i], Xvec[base + i], s);
        s += __shfl_xor_sync(0xffffffffu, s, 1);
        s += __shfl_xor_sync(0xffffffffu, s, 2);
        if ((l & 3) == 0) {
            if (w < 6) proj[w][l >> 2] = s;
            else       kb[l >> 2]      = s;
        }
    }

    // content: warp w handles m = w, w+8, w+16, w+24
#pragma unroll
    for (int mi = 0; mi < 4; mi++) {
        const int m = w + mi * 8;
        const int kidx = nbhd[(size_t)bn * Mq + m];
        const float* Kp = g_K + ((size_t)b * Nq + kidx) * Eq;
        float s = 0.f;
#pragma unroll
        for (int i = 0; i < 16; i += 4) {
            float4 kv = *(const float4*)(Kp + base + i);
            s = fmaf(kv.x, Qrow[base + i + 0], s);
            s = fmaf(kv.y, Qrow[base + i + 1], s);
            s = fmaf(kv.z, Qrow[base + i + 2], s);
            s = fmaf(kv.w, Qrow[base + i + 3], s);
        }
        s += __shfl_xor_sync(0xffffffffu, s, 1);
        s += __shfl_xor_sync(0xffffffffu, s, 2);
        if ((l & 3) == 0) cont[m][l >> 2] = s;
    }
    __syncthreads();

    // combine: thread t -> (m, h)
    const int m = tid >> 3;
    const int h = tid & 7;
    const float* plp = pl + ((size_t)bn * Mq + m) * Pq;
    float p = 0.f;
#pragma unroll
    for (int pp = 0; pp < Pq; pp++) p = fmaf(plp[pp], proj[pp][h], p);
    out[((size_t)bn * Mq + m) * Hq + h] = (cont[m][h] + p + kb[h]) * 0.125f;
}

// ---------------------------------------------------------------------------
// Launch
// Inputs (metadata order): 0 pairwise_locations, 1 mask (unused), 2 query_features,
// 3 key_features, 4 nbhd_idx, 5 Wq, 6 Wk, 7 Wl, 8 u, 9 v
// ---------------------------------------------------------------------------
extern "C" void kernel_launch(void* const* d_in, const int* in_sizes, int n_in,
                              void* d_out, int out_size)
{
    const float* pl   = (const float*)d_in[0];
    const float* qf   = (const float*)d_in[2];
    const float* kf   = (const float*)d_in[3];
    const int*   nb   = (const int*)  d_in[4];
    const float* Wq_  = (const float*)d_in[5];
    const float* Wk_  = (const float*)d_in[6];
    const float* Wl   = (const float*)d_in[7];
    const float* u    = (const float*)d_in[8];
    const float* v    = (const float*)d_in[9];
    float*       out  = (float*)d_out;

    dim3 gGrid(Eq / 128, (Bq * Nq) / 128, 2);   // 4 x 32 x 2
    gemm_qk_kernel<<<gGrid, 256>>>(qf, Wq_, kf, Wk_);

    fuse_kernel<<<Bq * Nq, 256>>>(pl, nb, Wl, u, v, out);
}

// round 2
// speedup vs baseline: 1.2102x; 1.2102x over previous
#include <cuda_runtime.h>

// Shapes (fixed by the problem)
#define Bq 2
#define Nq 2048
#define Mq 32
#define Hq 8
#define Dq 64
#define Eq 512
#define Fq 512
#define Pq 6

// Scratch: Q and K projections (graph-capture rules forbid cudaMalloc)
__device__ float g_Q[Bq * Nq * Eq];
__device__ float g_K[Bq * Nq * Eq];

// packed f32x2 FMA (PTX-only path; fp32 pipe is 2-wide for 64-bit packed ops)
__device__ __forceinline__ void ffma2(unsigned long long& d,
                                      unsigned long long a,
                                      unsigned long long b) {
    asm volatile("fma.rn.f32x2 %0, %1, %2, %0;" : "+l"(d) : "l"(a), "l"(b));
}
__device__ __forceinline__ unsigned long long dup2(float x) {
    unsigned long long r;
    asm("mov.b64 %0, {%1, %1};" : "=l"(r) : "r"(__float_as_uint(x)));
    return r;
}

// Bs column index: +4-word pad every 32 columns -> stride-32B ulonglong2 reads
// from 16 lanes hit distinct bank quads (conflict-free).
#define BIDX(c) ((c) + (((c) >> 5) << 2))
#define AS_STRIDE 132
#define BS_STRIDE 144

// ---------------------------------------------------------------------------
// GEMM: C[4096,512] = X[4096,512] @ W[512,512], fp32 via packed f32x2 FMA.
// 128x128 tile, TK=16, 256 threads, 8x8 microtile (4 f32x2 pairs over j).
// gridDim.z: 0 -> (query,Wq)->g_Q, 1 -> (key,Wk)->g_K.
// ---------------------------------------------------------------------------
__global__ __launch_bounds__(256) void gemm_qk_kernel(
    const float* __restrict__ Xq, const float* __restrict__ Wq_,
    const float* __restrict__ Xk, const float* __restrict__ Wk_)
{
    const float* X = blockIdx.z ? Xk : Xq;
    const float* W = blockIdx.z ? Wk_ : Wq_;
    float*       C = blockIdx.z ? g_K : g_Q;

    __shared__ float As[16][AS_STRIDE];   // As[k][row]
    __shared__ float Bs[16][BS_STRIDE];   // Bs[k][BIDX(col)]

    const int tid = threadIdx.x;
    const int ty = tid >> 4;              // 0..15
    const int tx = tid & 15;              // 0..15
    const int rowBase = blockIdx.y * 128;
    const int colBase = blockIdx.x * 128;

    // global->smem assignments (TK=16)
    const int arow = tid >> 1;            // 0..127
    const int akc  = (tid & 1) * 4;       // k-offsets {akc..akc+3, akc+8..akc+11}
    const int brow = tid >> 4;            // 0..15
    const int bcol = (tid & 15) * 8;      // 0..120

    unsigned long long acc2[8][4];
#pragma unroll
    for (int i = 0; i < 8; i++)
#pragma unroll
        for (int j = 0; j < 4; j++) acc2[i][j] = 0ull;

    // preload tile kt=0 into registers
    float4 a4a = *(const float4*)(X + (size_t)(rowBase + arow) * Fq + akc);
    float4 a4b = *(const float4*)(X + (size_t)(rowBase + arow) * Fq + akc + 8);
    float4 b4a = *(const float4*)(W + (size_t)brow * Eq + colBase + bcol);
    float4 b4b = *(const float4*)(W + (size_t)brow * Eq + colBase + bcol + 4);

    for (int kt = 0; kt < Fq; kt += 16) {
        __syncthreads();   // previous compute done -> safe to overwrite smem

        As[akc + 0][arow] = a4a.x;  As[akc + 1][arow] = a4a.y;
        As[akc + 2][arow] = a4a.z;  As[akc + 3][arow] = a4a.w;
        As[akc + 8][arow] = a4b.x;  As[akc + 9][arow] = a4b.y;
        As[akc + 10][arow] = a4b.z; As[akc + 11][arow] = a4b.w;
        *(float4*)&Bs[brow][BIDX(bcol)]     = b4a;
        *(float4*)&Bs[brow][BIDX(bcol) + 4] = b4b;

        __syncthreads();

        if (kt + 16 < Fq) {  // software pipeline: next tile overlaps compute
            a4a = *(const float4*)(X + (size_t)(rowBase + arow) * Fq + kt + 16 + akc);
            a4b = *(const float4*)(X + (size_t)(rowBase + arow) * Fq + kt + 16 + akc + 8);
            b4a = *(const float4*)(W + (size_t)(kt + 16 + brow) * Eq + colBase + bcol);
            b4b = *(const float4*)(W + (size_t)(kt + 16 + brow) * Eq + colBase + bcol + 4);
        }

#pragma unroll
        for (int k = 0; k < 16; k++) {
            float4 af0 = *(const float4*)&As[k][ty * 8];
            float4 af1 = *(const float4*)&As[k][ty * 8 + 4];
            ulonglong2 bp0 = *(const ulonglong2*)&Bs[k][BIDX(tx * 8)];
            ulonglong2 bp1 = *(const ulonglong2*)&Bs[k][BIDX(tx * 8) + 4];
            unsigned long long bq[4] = {bp0.x, bp0.y, bp1.x, bp1.y};
            unsigned long long ad[8] = {dup2(af0.x), dup2(af0.y), dup2(af0.z), dup2(af0.w),
                                        dup2(af1.x), dup2(af1.y), dup2(af1.z), dup2(af1.w)};
#pragma unroll
            for (int i = 0; i < 8; i++)
#pragma unroll
                for (int j = 0; j < 4; j++)
                    ffma2(acc2[i][j], ad[i], bq[j]);
        }
    }

    float* Cp = C + (size_t)(rowBase + ty * 8) * Eq + colBase + tx * 8;
#pragma unroll
    for (int i = 0; i < 8; i++) {
        // f32x2 lanes are (low=j, high=j+1) -> contiguous store is correct
        *(ulonglong2*)(Cp + (size_t)i * Eq)     = make_ulonglong2(acc2[i][0], acc2[i][1]);
        *(ulonglong2*)(Cp + (size_t)i * Eq + 4) = make_ulonglong2(acc2[i][2], acc2[i][3]);
    }
}

// ---------------------------------------------------------------------------
// Fused epilogue: one CTA (256 thr, 8 warps) per token (b,n).
// Lane l owns elements [l*16, l*16+16) of the 512-wide row; head h = l/4,
// reductions over the 4-lane group via shfl_xor(1), shfl_xor(2).
// Q slice lives in REGISTERS (no smem staging -> no LDS in the hot loop).
//   proj[p,h] = sum_d Wl[p,:]*(Q+v)      (warps 0..5)
//   kb[h]     = sum_d K*u                (warp 6)
//   cont[m,h] = sum_d Q*K[nbhd[m]]       (all warps, 4 m each)
//   A = (cont + pos + kb) / 8,  pos = sum_p pl*proj
// ---------------------------------------------------------------------------
__global__ __launch_bounds__(256) void fuse_kernel(
    const float* __restrict__ pl,     // (B,N,M,P)
    const int*   __restrict__ nbhd,   // (B,N,M)
    const float* __restrict__ Wl,     // (P,E)
    const float* __restrict__ u,      // (H,1,D) = 512 contiguous
    const float* __restrict__ v,      // (H,1,D) = 512 contiguous
    float*       __restrict__ out)    // (B,N,M,H)
{
    const int bn = blockIdx.x;        // 0..4095
    const int b  = bn >> 11;

    __shared__ float proj[Pq][Hq];
    __shared__ float kb[Hq];
    __shared__ float cont[Mq][Hq];

    const int tid = threadIdx.x;
    const int w = tid >> 5;
    const int l = tid & 31;
    const int base = l * 16;

    // lane's 16 Q values -> registers
    const float* Qg = g_Q + (size_t)bn * Eq + base;
    float4 q0 = *(const float4*)(Qg + 0);
    float4 q1 = *(const float4*)(Qg + 4);
    float4 q2 = *(const float4*)(Qg + 8);
    float4 q3 = *(const float4*)(Qg + 12);
    float qr[16] = {q0.x, q0.y, q0.z, q0.w, q1.x, q1.y, q1.z, q1.w,
                    q2.x, q2.y, q2.z, q2.w, q3.x, q3.y, q3.z, q3.w};

    // proj (warps 0..5) / key_bias (warp 6)
    if (w < 6) {
        const float* wl = Wl + w * Eq + base;
        const float* vv = v + base;
        float s = 0.f;
#pragma unroll
        for (int i = 0; i < 16; i += 4) {
            float4 wv = *(const float4*)(wl + i);
            float4 vf = *(const float4*)(vv + i);
            s = fmaf(wv.x, qr[i + 0] + vf.x, s);
            s = fmaf(wv.y, qr[i + 1] + vf.y, s);
            s = fmaf(wv.z, qr[i + 2] + vf.z, s);
            s = fmaf(wv.w, qr[i + 3] + vf.w, s);
        }
        s += __shfl_xor_sync(0xffffffffu, s, 1);
        s += __shfl_xor_sync(0xffffffffu, s, 2);
        if ((l & 3) == 0) proj[w][l >> 2] = s;
    } else if (w == 6) {
        const float* Kg = g_K + (size_t)bn * Eq + base;
        const float* uu = u + base;
        float s = 0.f;
#pragma unroll
        for (int i = 0; i < 16; i += 4) {
            float4 kf = *(const float4*)(Kg + i);
            float4 uf = *(const float4*)(uu + i);
            s = fmaf(kf.x, uf.x, s);
            s = fmaf(kf.y, uf.y, s);
            s = fmaf(kf.z, uf.z, s);
            s = fmaf(kf.w, uf.w, s);
        }
        s += __shfl_xor_sync(0xffffffffu, s, 1);
        s += __shfl_xor_sync(0xffffffffu, s, 2);
        if ((l & 3) == 0) kb[l >> 2] = s;
    }

    // content: warp w handles m = w, w+8, w+16, w+24; 2 m in flight for MLP
    const float* Kbase = g_K + ((size_t)b * Nq) * Eq + base;
    const int* nbp = nbhd + (size_t)bn * Mq;
#pragma unroll
    for (int mi = 0; mi < 4; mi += 2) {
        const int m0 = w + mi * 8;
        const int m1 = w + (mi + 1) * 8;
        const float* Kp0 = Kbase + (size_t)nbp[m0] * Eq;
        const float* Kp1 = Kbase + (size_t)nbp[m1] * Eq;
        float4 k00 = *(const float4*)(Kp0 + 0);
        float4 k01 = *(const float4*)(Kp0 + 4);
        float4 k02 = *(const float4*)(Kp0 + 8);
        float4 k03 = *(const float4*)(Kp0 + 12);
        float4 k10 = *(const float4*)(Kp1 + 0);
        float4 k11 = *(const float4*)(Kp1 + 4);
        float4 k12 = *(const float4*)(Kp1 + 8);
        float4 k13 = *(const float4*)(Kp1 + 12);

        float s0 = 0.f, s1 = 0.f;
        s0 = fmaf(k00.x, qr[0], s0);  s0 = fmaf(k00.y, qr[1], s0);
        s0 = fmaf(k00.z, qr[2], s0);  s0 = fmaf(k00.w, qr[3], s0);
        s0 = fmaf(k01.x, qr[4], s0);  s0 = fmaf(k01.y, qr[5], s0);
        s0 = fmaf(k01.z, qr[6], s0);  s0 = fmaf(k01.w, qr[7], s0);
        s0 = fmaf(k02.x, qr[8], s0);  s0 = fmaf(k02.y, qr[9], s0);
        s0 = fmaf(k02.z, qr[10], s0); s0 = fmaf(k02.w, qr[11], s0);
        s0 = fmaf(k03.x, qr[12], s0); s0 = fmaf(k03.y, qr[13], s0);
        s0 = fmaf(k03.z, qr[14], s0); s0 = fmaf(k03.w, qr[15], s0);

        s1 = fmaf(k10.x, qr[0], s1);  s1 = fmaf(k10.y, qr[1], s1);
        s1 = fmaf(k10.z, qr[2], s1);  s1 = fmaf(k10.w, qr[3], s1);
        s1 = fmaf(k11.x, qr[4], s1);  s1 = fmaf(k11.y, qr[5], s1);
        s1 = fmaf(k11.z, qr[6], s1);  s1 = fmaf(k11.w, qr[7], s1);
        s1 = fmaf(k12.x, qr[8], s1);  s1 = fmaf(k12.y, qr[9], s1);
        s1 = fmaf(k12.z, qr[10], s1); s1 = fmaf(k12.w, qr[11], s1);
        s1 = fmaf(k13.x, qr[12], s1); s1 = fmaf(k13.y, qr[13], s1);
        s1 = fmaf(k13.z, qr[14], s1); s1 = fmaf(k13.w, qr[15], s1);

        s0 += __shfl_xor_sync(0xffffffffu, s0, 1);
        s0 += __shfl_xor_sync(0xffffffffu, s0, 2);
        s1 += __shfl_xor_sync(0xffffffffu, s1, 1);
        s1 += __shfl_xor_sync(0xffffffffu, s1, 2);
        if ((l & 3) == 0) {
            cont[m0][l >> 2] = s0;
            cont[m1][l >> 2] = s1;
        }
    }
    __syncthreads();

    // combine: thread t -> (m, h)
    const int m = tid >> 3;
    const int h = tid & 7;
    const float* plp = pl + ((size_t)bn * Mq + m) * Pq;
    float p = 0.f;
#pragma unroll
    for (int pp = 0; pp < Pq; pp++) p = fmaf(plp[pp], proj[pp][h], p);
    out[((size_t)bn * Mq + m) * Hq + h] = (cont[m][h] + p + kb[h]) * 0.125f;
}

// ---------------------------------------------------------------------------
// Launch
// Inputs: 0 pairwise_locations, 1 mask (unused), 2 query_features,
// 3 key_features, 4 nbhd_idx, 5 Wq, 6 Wk, 7 Wl, 8 u, 9 v
// ---------------------------------------------------------------------------
extern "C" void kernel_launch(void* const* d_in, const int* in_sizes, int n_in,
                              void* d_out, int out_size)
{
    const float* pl   = (const float*)d_in[0];
    const float* qf   = (const float*)d_in[2];
    const float* kf   = (const float*)d_in[3];
    const int*   nb   = (const int*)  d_in[4];
    const float* Wq_  = (const float*)d_in[5];
    const float* Wk_  = (const float*)d_in[6];
    const float* Wl   = (const float*)d_in[7];
    const float* u    = (const float*)d_in[8];
    const float* v    = (const float*)d_in[9];
    float*       out  = (float*)d_out;

    dim3 gGrid(Eq / 128, (Bq * Nq) / 128, 2);   // 4 x 32 x 2
    gemm_qk_kernel<<<gGrid, 256>>>(qf, Wq_, kf, Wk_);

    fuse_kernel<<<Bq * Nq, 256>>>(pl, nb, Wl, u, v, out);
}

// round 4
// speedup vs baseline: 2.3597x; 1.9499x over previous
#include <cuda_runtime.h>
#include <cuda_bf16.h>
#include <cstdint>

// Shapes (fixed by the problem)
#define Bq 2
#define Nq 2048
#define Mq 32
#define Hq 8
#define Dq 64
#define Eq 512
#define Fq 512
#define Pq 6

// ---------------------------------------------------------------------------
// Scratch (graph-capture rules forbid cudaMalloc)
// ---------------------------------------------------------------------------
__device__ float g_Q[Bq * Nq * Eq];
__device__ float g_K[Bq * Nq * Eq];
__device__ __nv_bfloat16 g_qh[Bq * Nq * Fq];
__device__ __nv_bfloat16 g_ql[Bq * Nq * Fq];
__device__ __nv_bfloat16 g_kh[Bq * Nq * Fq];
__device__ __nv_bfloat16 g_kl[Bq * Nq * Fq];
// transposed weights: [n][k]
__device__ __nv_bfloat16 g_wqh[Eq * Fq];
__device__ __nv_bfloat16 g_wql[Eq * Fq];
__device__ __nv_bfloat16 g_wkh[Eq * Fq];
__device__ __nv_bfloat16 g_wkl[Eq * Fq];

// ---------------------------------------------------------------------------
// helpers
// ---------------------------------------------------------------------------
__device__ __forceinline__ uint32_t smem_u32(const void* p) {
    uint32_t a;
    asm("{ .reg .u64 t; cvta.to.shared.u64 t, %1; cvt.u32.u64 %0, t; }" : "=r"(a) : "l"(p));
    return a;
}
__device__ __forceinline__ void cpasync16(uint32_t s, const void* g) {
    asm volatile("cp.async.cg.shared.global [%0], [%1], 16;" :: "r"(s), "l"(g));
}
__device__ __forceinline__ void ldsm_x4(uint32_t& r0, uint32_t& r1, uint32_t& r2, uint32_t& r3,
                                        uint32_t addr) {
    asm volatile("ldmatrix.sync.aligned.m8n8.x4.shared.b16 {%0,%1,%2,%3}, [%4];"
                 : "=r"(r0), "=r"(r1), "=r"(r2), "=r"(r3) : "r"(addr));
}
__device__ __forceinline__ void mma_bf16(float* c, const uint32_t* a, uint32_t b0, uint32_t b1) {
    asm volatile(
        "mma.sync.aligned.m16n8k16.row.col.f32.bf16.bf16.f32 "
        "{%0,%1,%2,%3}, {%4,%5,%6,%7}, {%8,%9}, {%0,%1,%2,%3};"
        : "+f"(c[0]), "+f"(c[1]), "+f"(c[2]), "+f"(c[3])
        : "r"(a[0]), "r"(a[1]), "r"(a[2]), "r"(a[3]), "r"(b0), "r"(b1));
}

// ---------------------------------------------------------------------------
// split_x: fp32 -> bf16 hi/lo for qf and kf (blockIdx.y selects matrix)
// ---------------------------------------------------------------------------
__global__ __launch_bounds__(256) void split_x_kernel(
    const float* __restrict__ qf, const float* __restrict__ kf)
{
    const int f4 = blockIdx.x * 256 + threadIdx.x;          // 0..524287
    const float* in = blockIdx.y ? kf : qf;
    __nv_bfloat16* oh = blockIdx.y ? g_kh : g_qh;
    __nv_bfloat16* ol = blockIdx.y ? g_kl : g_ql;

    float4 x = ((const float4*)in)[f4];
    float xs[4] = {x.x, x.y, x.z, x.w};
    uint32_t hp[2] = {0, 0}, lp[2] = {0, 0};
#pragma unroll
    for (int i = 0; i < 4; i++) {
        __nv_bfloat16 hb = __float2bfloat16(xs[i]);
        float r = xs[i] - __bfloat162float(hb);
        __nv_bfloat16 lb = __float2bfloat16(r);
        hp[i >> 1] |= (uint32_t)__bfloat16_as_ushort(hb) << ((i & 1) * 16);
        lp[i >> 1] |= (uint32_t)__bfloat16_as_ushort(lb) << ((i & 1) * 16);
    }
    ((uint2*)oh)[f4] = make_uint2(hp[0], hp[1]);
    ((uint2*)ol)[f4] = make_uint2(lp[0], lp[1]);
}

// ---------------------------------------------------------------------------
// split_wt: W [k][n] -> transposed bf16 hi/lo [n][k] (smem tile transpose)
// ---------------------------------------------------------------------------
__global__ void split_wt_kernel(const float* __restrict__ Wq_, const float* __restrict__ Wk_)
{
    __shared__ float tile[32][33];
    const float* in = blockIdx.z ? Wk_ : Wq_;
    __nv_bfloat16* oh = blockIdx.z ? g_wkh : g_wqh;
    __nv_bfloat16* ol = blockIdx.z ? g_wkl : g_wql;

    const int tx = threadIdx.x, ty = threadIdx.y;
    const int n0 = blockIdx.x * 32, k0 = blockIdx.y * 32;
#pragma unroll
    for (int j = 0; j < 4; j++)
        tile[ty + j * 8][tx] = in[(size_t)(k0 + ty + j * 8) * Eq + n0 + tx];
    __syncthreads();
#pragma unroll
    for (int j = 0; j < 4; j++) {
        float val = tile[tx][ty + j * 8];
        __nv_bfloat16 hb = __float2bfloat16(val);
        float r = val - __bfloat162float(hb);
        size_t o = (size_t)(n0 + ty + j * 8) * Fq + k0 + tx;
        oh[o] = hb;
        ol[o] = __float2bfloat16(r);
    }
}

// ---------------------------------------------------------------------------
// GEMM via mma.sync bf16x3: C[4096,512] = Xh*Wh + Xh*Wl + Xl*Wh.
// CTA tile 128x128, 8 warps (2x4), warp tile 64x32 (4x4 m16n8k16).
// K-chunk 32, double-buffered cp.async. grid (4, 32, 2), 256 thr.
// smem rows padded: stride 40 bf16 = 80B -> LDSM conflict-free.
// ---------------------------------------------------------------------------
#define KC 32
#define LDE 40                       // elements per smem row
#define TILE_B (128 * LDE * 2)       // 10240 bytes per tile
#define BUF_B (4 * TILE_B)           // Ah, Al, Bh, Bl
#define GEMM_SMEM (2 * BUF_B)        // 81920

__global__ __launch_bounds__(256, 2) void gemm_tc_kernel()
{
    extern __shared__ char smem[];
    const uint32_t sbase = smem_u32(smem);
    const int tid = threadIdx.x;
    const int wid = tid >> 5;
    const int lane = tid & 31;
    const int z = blockIdx.z;
    const int rowBase = blockIdx.y * 128;
    const int colBase = blockIdx.x * 128;

    const __nv_bfloat16* Xh = z ? g_kh : g_qh;
    const __nv_bfloat16* Xl = z ? g_kl : g_ql;
    const __nv_bfloat16* Wh = z ? g_wkh : g_wqh;
    const __nv_bfloat16* Wl = z ? g_wkl : g_wql;
    float* C = z ? g_K : g_Q;

    const int wm = (wid >> 2) * 64;   // warp m offset (0 or 64)
    const int wn = (wid & 3) * 32;    // warp n offset

    // staging indices: idx 0..511 per tile -> row = idx>>2, seg = idx&3
    const int r0a = tid >> 2, s0 = (tid & 3) * 8;
    const int r1a = (tid + 256) >> 2;

    float acc[4][4][4];
#pragma unroll
    for (int mt = 0; mt < 4; mt++)
#pragma unroll
        for (int nt = 0; nt < 4; nt++)
#pragma unroll
            for (int i = 0; i < 4; i++) acc[mt][nt][i] = 0.f;

    auto stage = [&](int buf, int kt) {
        const uint32_t sb = sbase + buf * BUF_B;
#pragma unroll
        for (int t = 0; t < 2; t++) {
            const int row = t ? r1a : r0a;
            const uint32_t so = (uint32_t)(row * LDE + s0) * 2;
            const size_t ga = (size_t)(rowBase + row) * Fq + kt + s0;
            const size_t gb = (size_t)(colBase + row) * Fq + kt + s0;
            cpasync16(sb + so,              Xh + ga);
            cpasync16(sb + TILE_B + so,     Xl + ga);
            cpasync16(sb + 2 * TILE_B + so, Wh + gb);
            cpasync16(sb + 3 * TILE_B + so, Wl + gb);
        }
        asm volatile("cp.async.commit_group;");
    };

    // LDSM lane address components
    const int lj = lane >> 3, lr = lane & 7;
    const int arow = (lj & 1) * 8 + lr;       // A: matrices (m0,k0),(m8,k0),(m0,k8),(m8,k8)
    const int acol = (lj >> 1) * 8;
    const int brow = (lj >> 1) * 8 + lr;      // B: matrices (nA,k0),(nA,k8),(nB,k0),(nB,k8)
    const int bcol = (lj & 1) * 8;

    stage(0, 0);

    const int NCHUNK = Fq / KC;               // 16
    for (int c = 0; c < NCHUNK; c++) {
        if (c + 1 < NCHUNK) stage((c + 1) & 1, (c + 1) * KC);
        if (c + 1 < NCHUNK) asm volatile("cp.async.wait_group 1;");
        else                asm volatile("cp.async.wait_group 0;");
        __syncthreads();

        const uint32_t sb = sbase + (c & 1) * BUF_B;
#pragma unroll
        for (int ks = 0; ks < 2; ks++) {
            const int kof = ks * 16;
            uint32_t ah[4][4], bh[2][4], bl[2][4], al[4][4];
            // A-hi fragments (4 m-tiles)
#pragma unroll
            for (int mt = 0; mt < 4; mt++)
                ldsm_x4(ah[mt][0], ah[mt][1], ah[mt][2], ah[mt][3],
                        sb + (uint32_t)((wm + mt * 16 + arow) * LDE + kof + acol) * 2);
            // B-hi fragments (2 n-pairs)
#pragma unroll
            for (int np = 0; np < 2; np++)
                ldsm_x4(bh[np][0], bh[np][1], bh[np][2], bh[np][3],
                        sb + 2 * TILE_B + (uint32_t)((wn + np * 16 + brow) * LDE + kof + bcol) * 2);
            // HH
#pragma unroll
            for (int mt = 0; mt < 4; mt++)
#pragma unroll
                for (int nt = 0; nt < 4; nt++)
                    mma_bf16(acc[mt][nt], ah[mt],
                             bh[nt >> 1][(nt & 1) * 2], bh[nt >> 1][(nt & 1) * 2 + 1]);
            // B-lo fragments
#pragma unroll
            for (int np = 0; np < 2; np++)
                ldsm_x4(bl[np][0], bl[np][1], bl[np][2], bl[np][3],
                        sb + 3 * TILE_B + (uint32_t)((wn + np * 16 + brow) * LDE + kof + bcol) * 2);
            // HL
#pragma unroll
            for (int mt = 0; mt < 4; mt++)
#pragma unroll
                for (int nt = 0; nt < 4; nt++)
                    mma_bf16(acc[mt][nt], ah[mt],
                             bl[nt >> 1][(nt & 1) * 2], bl[nt >> 1][(nt & 1) * 2 + 1]);
            // A-lo fragments
#pragma unroll
            for (int mt = 0; mt < 4; mt++)
                ldsm_x4(al[mt][0], al[mt][1], al[mt][2], al[mt][3],
                        sb + TILE_B + (uint32_t)((wm + mt * 16 + arow) * LDE + kof + acol) * 2);
            // LH
#pragma unroll
            for (int mt = 0; mt < 4; mt++)
#pragma unroll
                for (int nt = 0; nt < 4; nt++)
                    mma_bf16(acc[mt][nt], al[mt],
                             bh[nt >> 1][(nt & 1) * 2], bh[nt >> 1][(nt & 1) * 2 + 1]);
        }
        __syncthreads();
    }

    // epilogue: acc layout m16n8: thread t: rows g, g+8 (g=t/4), cols 2*(t%4)
    const int g = lane >> 2, tg = lane & 3;
#pragma unroll
    for (int mt = 0; mt < 4; mt++) {
#pragma unroll
        for (int nt = 0; nt < 4; nt++) {
            const int row = rowBase + wm + mt * 16 + g;
            const int col = colBase + wn + nt * 8 + 2 * tg;
            *(float2*)(C + (size_t)row * Eq + col) =
                make_float2(acc[mt][nt][0], acc[mt][nt][1]);
            *(float2*)(C + (size_t)(row + 8) * Eq + col) =
                make_float2(acc[mt][nt][2], acc[mt][nt][3]);
        }
    }
}

// ---------------------------------------------------------------------------
// Fused epilogue: one CTA (256 thr, 8 warps) per token (b,n).
// CHUNKED lane map: lane l reads float4 at element c*128 + l*4 (coalesced
// LDG.128). Element c*128+l*4+j belongs to head 2c + (l>=16); reduce each
// chunk over its 16-lane half via shfl_xor 1,2,4,8.
// ---------------------------------------------------------------------------
__device__ __forceinline__ float red16(float s) {
    s += __shfl_xor_sync(0xffffffffu, s, 1);
    s += __shfl_xor_sync(0xffffffffu, s, 2);
    s += __shfl_xor_sync(0xffffffffu, s, 4);
    s += __shfl_xor_sync(0xffffffffu, s, 8);
    return s;
}

__global__ __launch_bounds__(256) void fuse_kernel(
    const float* __restrict__ pl,     // (B,N,M,P)
    const int*   __restrict__ nbhd,   // (B,N,M)
    const float* __restrict__ Wl,     // (P,E)
    const float* __restrict__ u,      // 512 contiguous
    const float* __restrict__ v,      // 512 contiguous
    float*       __restrict__ out)    // (B,N,M,H)
{
    const int bn = blockIdx.x;        // 0..4095
    const int b  = bn >> 11;

    __shared__ float proj[Pq][Hq];
    __shared__ float kb[Hq];
    __shared__ float cont[Mq][Hq];

    const int tid = threadIdx.x;
    const int w = tid >> 5;
    const int l = tid & 31;
    const int hsub = l >> 4;          // which head within chunk

    // own Q row, chunked into registers
    const float* Qg = g_Q + (size_t)bn * Eq;
    float4 q[4];
#pragma unroll
    for (int c = 0; c < 4; c++) q[c] = *(const float4*)(Qg + c * 128 + l * 4);

    if (w < 6) {
        const float* wlr = Wl + w * Eq;
#pragma unroll
        for (int c = 0; c < 4; c++) {
            float4 wv = *(const float4*)(wlr + c * 128 + l * 4);
            float4 vf = *(const float4*)(v + c * 128 + l * 4);
            float s = 0.f;
            s = fmaf(wv.x, q[c].x + vf.x, s);
            s = fmaf(wv.y, q[c].y + vf.y, s);
            s = fmaf(wv.z, q[c].z + vf.z, s);
            s = fmaf(wv.w, q[c].w + vf.w, s);
            s = red16(s);
            if ((l & 15) == 0) proj[w][2 * c + hsub] = s;
        }
    } else if (w == 6) {
        const float* Kg = g_K + (size_t)bn * Eq;
#pragma unroll
        for (int c = 0; c < 4; c++) {
            float4 kf = *(const float4*)(Kg + c * 128 + l * 4);
            float4 uf = *(const float4*)(u + c * 128 + l * 4);
            float s = 0.f;
            s = fmaf(kf.x, uf.x, s);
            s = fmaf(kf.y, uf.y, s);
            s = fmaf(kf.z, uf.z, s);
            s = fmaf(kf.w, uf.w, s);
            s = red16(s);
            if ((l & 15) == 0) kb[2 * c + hsub] = s;
        }
    }

    // content: warp w handles m = w, w+8, w+16, w+24; 2 rows in flight
    const float* Kbase = g_K + (size_t)b * Nq * Eq;
    const int* nbp = nbhd + (size_t)bn * Mq;
#pragma unroll
    for (int mi = 0; mi < 4; mi += 2) {
        const int m0 = w + mi * 8;
        const int m1 = w + (mi + 1) * 8;
        const float* Kp0 = Kbase + (size_t)nbp[m0] * Eq;
        const float* Kp1 = Kbase + (size_t)nbp[m1] * Eq;
        float4 k0[4], k1[4];
#pragma unroll
        for (int c = 0; c < 4; c++) {
            k0[c] = *(const float4*)(Kp0 + c * 128 + l * 4);
            k1[c] = *(const float4*)(Kp1 + c * 128 + l * 4);
        }
#pragma unroll
        for (int c = 0; c < 4; c++) {
            float s0 = 0.f, s1 = 0.f;
            s0 = fmaf(k0[c].x, q[c].x, s0);
            s0 = fmaf(k0[c].y, q[c].y, s0);
            s0 = fmaf(k0[c].z, q[c].z, s0);
            s0 = fmaf(k0[c].w, q[c].w, s0);
            s1 = fmaf(k1[c].x, q[c].x, s1);
            s1 = fmaf(k1[c].y, q[c].y, s1);
            s1 = fmaf(k1[c].z, q[c].z, s1);
            s1 = fmaf(k1[c].w, q[c].w, s1);
            s0 = red16(s0);
            s1 = red16(s1);
            if ((l & 15) == 0) {
                cont[m0][2 * c + hsub] = s0;
                cont[m1][2 * c + hsub] = s1;
            }
        }
    }
    __syncthreads();

    // combine: thread t -> (m, h)
    const int m = tid >> 3;
    const int h = tid & 7;
    const float* plp = pl + ((size_t)bn * Mq + m) * Pq;
    float p = 0.f;
#pragma unroll
    for (int pp = 0; pp < Pq; pp++) p = fmaf(plp[pp], proj[pp][h], p);
    out[((size_t)bn * Mq + m) * Hq + h] = (cont[m][h] + p + kb[h]) * 0.125f;
}

// ---------------------------------------------------------------------------
// Launch
// Inputs: 0 pairwise_locations, 1 mask (unused), 2 query_features,
// 3 key_features, 4 nbhd_idx, 5 Wq, 6 Wk, 7 Wl, 8 u, 9 v
// ---------------------------------------------------------------------------
extern "C" void kernel_launch(void* const* d_in, const int* in_sizes, int n_in,
                              void* d_out, int out_size)
{
    const float* pl   = (const float*)d_in[0];
    const float* qf   = (const float*)d_in[2];
    const float* kf   = (const float*)d_in[3];
    const int*   nb   = (const int*)  d_in[4];
    const float* Wq_  = (const float*)d_in[5];
    const float* Wk_  = (const float*)d_in[6];
    const float* Wl   = (const float*)d_in[7];
    const float* u    = (const float*)d_in[8];
    const float* v    = (const float*)d_in[9];
    float*       out  = (float*)d_out;

    static int smem_set = 0;
    if (!smem_set) {
        cudaFuncSetAttribute(gemm_tc_kernel,
                             cudaFuncAttributeMaxDynamicSharedMemorySize, GEMM_SMEM);
        smem_set = 1;
    }

    split_x_kernel<<<dim3(2048, 2), 256>>>(qf, kf);
    split_wt_kernel<<<dim3(16, 16, 2), dim3(32, 8)>>>(Wq_, Wk_);
    gemm_tc_kernel<<<dim3(4, 32, 2), 256, GEMM_SMEM>>>();
    fuse_kernel<<<Bq * Nq, 256>>>(pl, nb, Wl, u, v, out);
}

// round 5
// speedup vs baseline: 2.6139x; 1.1077x over previous
#include <cuda_runtime.h>
#include <cuda_bf16.h>
#include <cuda_fp16.h>
#include <cstdint>

// Shapes (fixed by the problem)
#define Bq 2
#define Nq 2048
#define Mq 32
#define Hq 8
#define Dq 64
#define Eq 512
#define Fq 512
#define Pq 6

// ---------------------------------------------------------------------------
// Scratch (graph-capture rules forbid cudaMalloc)
// ---------------------------------------------------------------------------
__device__ float  g_Q [Bq * Nq * Eq];     // fp32 Q projections (proj path)
__device__ __half g_Kh[Bq * Nq * Eq];     // fp16 K projections (gather + kb)
__device__ __nv_bfloat16 g_qh[Bq * Nq * Fq];
__device__ __nv_bfloat16 g_ql[Bq * Nq * Fq];
__device__ __nv_bfloat16 g_kh[Bq * Nq * Fq];
__device__ __nv_bfloat16 g_kl[Bq * Nq * Fq];
// transposed weights: [n][k]
__device__ __nv_bfloat16 g_wqh[Eq * Fq];
__device__ __nv_bfloat16 g_wql[Eq * Fq];
__device__ __nv_bfloat16 g_wkh[Eq * Fq];
__device__ __nv_bfloat16 g_wkl[Eq * Fq];

// ---------------------------------------------------------------------------
// helpers
// ---------------------------------------------------------------------------
__device__ __forceinline__ uint32_t smem_u32(const void* p) {
    uint32_t a;
    asm("{ .reg .u64 t; cvta.to.shared.u64 t, %1; cvt.u32.u64 %0, t; }" : "=r"(a) : "l"(p));
    return a;
}
__device__ __forceinline__ void cpasync16(uint32_t s, const void* g) {
    asm volatile("cp.async.cg.shared.global [%0], [%1], 16;" :: "r"(s), "l"(g));
}
__device__ __forceinline__ void ldsm_x4(uint32_t& r0, uint32_t& r1, uint32_t& r2, uint32_t& r3,
                                        uint32_t addr) {
    asm volatile("ldmatrix.sync.aligned.m8n8.x4.shared.b16 {%0,%1,%2,%3}, [%4];"
                 : "=r"(r0), "=r"(r1), "=r"(r2), "=r"(r3) : "r"(addr));
}
__device__ __forceinline__ void mma_bf16(float* c, const uint32_t* a, uint32_t b0, uint32_t b1) {
    asm volatile(
        "mma.sync.aligned.m16n8k16.row.col.f32.bf16.bf16.f32 "
        "{%0,%1,%2,%3}, {%4,%5,%6,%7}, {%8,%9}, {%0,%1,%2,%3};"
        : "+f"(c[0]), "+f"(c[1]), "+f"(c[2]), "+f"(c[3])
        : "r"(a[0]), "r"(a[1]), "r"(a[2]), "r"(a[3]), "r"(b0), "r"(b1));
}
// 8 packed halves (one uint4) -> 8 floats
__device__ __forceinline__ void h8_to_f(const uint4& kv, float* f) {
    const __half2* hp = reinterpret_cast<const __half2*>(&kv);
#pragma unroll
    for (int i = 0; i < 4; i++) {
        float2 t = __half22float2(hp[i]);
        f[2 * i] = t.x;
        f[2 * i + 1] = t.y;
    }
}

// ---------------------------------------------------------------------------
// prep: merged split_x (blocks 0..2047) + split_wt (blocks 2048..2303).
// z = 0 -> (qf, Wq); z = 1 -> (kf, Wk).
// ---------------------------------------------------------------------------
__global__ __launch_bounds__(256) void prep_kernel(
    const float* __restrict__ qf, const float* __restrict__ kf,
    const float* __restrict__ Wq_, const float* __restrict__ Wk_)
{
    __shared__ float tile[32][33];
    const int z = blockIdx.z;
    const int tid = threadIdx.x;

    if (blockIdx.x < 2048) {
        // ---- split X: fp32 -> bf16 hi/lo ----
        const int f4 = blockIdx.x * 256 + tid;
        const float* in = z ? kf : qf;
        __nv_bfloat16* oh = z ? g_kh : g_qh;
        __nv_bfloat16* ol = z ? g_kl : g_ql;

        float4 x = ((const float4*)in)[f4];
        float xs[4] = {x.x, x.y, x.z, x.w};
        uint32_t hp[2] = {0, 0}, lp[2] = {0, 0};
#pragma unroll
        for (int i = 0; i < 4; i++) {
            __nv_bfloat16 hb = __float2bfloat16(xs[i]);
            float r = xs[i] - __bfloat162float(hb);
            __nv_bfloat16 lb = __float2bfloat16(r);
            hp[i >> 1] |= (uint32_t)__bfloat16_as_ushort(hb) << ((i & 1) * 16);
            lp[i >> 1] |= (uint32_t)__bfloat16_as_ushort(lb) << ((i & 1) * 16);
        }
        ((uint2*)oh)[f4] = make_uint2(hp[0], hp[1]);
        ((uint2*)ol)[f4] = make_uint2(lp[0], lp[1]);
    } else {
        // ---- split + transpose W: [k][n] -> bf16 hi/lo [n][k] ----
        const int bx = blockIdx.x - 2048;           // 0..255
        const float* in = z ? Wk_ : Wq_;
        __nv_bfloat16* oh = z ? g_wkh : g_wqh;
        __nv_bfloat16* ol = z ? g_wkl : g_wql;

        const int tx = tid & 31, ty = tid >> 5;     // 32 x 8
        const int n0 = (bx & 15) * 32, k0 = (bx >> 4) * 32;
#pragma unroll
        for (int j = 0; j < 4; j++)
            tile[ty + j * 8][tx] = in[(size_t)(k0 + ty + j * 8) * Eq + n0 + tx];
        __syncthreads();
#pragma unroll
        for (int j = 0; j < 4; j++) {
            float val = tile[tx][ty + j * 8];
            __nv_bfloat16 hb = __float2bfloat16(val);
            float r = val - __bfloat162float(hb);
            size_t o = (size_t)(n0 + ty + j * 8) * Fq + k0 + tx;
            oh[o] = hb;
            ol[o] = __float2bfloat16(r);
        }
    }
}

// ---------------------------------------------------------------------------
// GEMM via mma.sync bf16x3: C = Xh*Wh + Xh*Wl + Xl*Wh.
// CTA tile 128x128, 8 warps (2x4), warp tile 64x32 (4x4 m16n8k16).
// K-chunk 32, double-buffered cp.async. grid (4, 32, 2), 256 thr.
// z=0 writes fp32 g_Q; z=1 writes fp16 g_Kh.
// ---------------------------------------------------------------------------
#define KC 32
#define LDE 40                       // elements per smem row (80B: LDSM conflict-free)
#define TILE_B (128 * LDE * 2)       // 10240 bytes per tile
#define BUF_B (4 * TILE_B)           // Ah, Al, Bh, Bl
#define GEMM_SMEM (2 * BUF_B)        // 81920

__global__ __launch_bounds__(256, 2) void gemm_tc_kernel()
{
    extern __shared__ char smem[];
    const uint32_t sbase = smem_u32(smem);
    const int tid = threadIdx.x;
    const int wid = tid >> 5;
    const int lane = tid & 31;
    const int z = blockIdx.z;
    const int rowBase = blockIdx.y * 128;
    const int colBase = blockIdx.x * 128;

    const __nv_bfloat16* Xh = z ? g_kh : g_qh;
    const __nv_bfloat16* Xl = z ? g_kl : g_ql;
    const __nv_bfloat16* Wh = z ? g_wkh : g_wqh;
    const __nv_bfloat16* Wl = z ? g_wkl : g_wql;

    const int wm = (wid >> 2) * 64;
    const int wn = (wid & 3) * 32;

    const int r0a = tid >> 2, s0 = (tid & 3) * 8;
    const int r1a = (tid + 256) >> 2;

    float acc[4][4][4];
#pragma unroll
    for (int mt = 0; mt < 4; mt++)
#pragma unroll
        for (int nt = 0; nt < 4; nt++)
#pragma unroll
            for (int i = 0; i < 4; i++) acc[mt][nt][i] = 0.f;

    auto stage = [&](int buf, int kt) {
        const uint32_t sb = sbase + buf * BUF_B;
#pragma unroll
        for (int t = 0; t < 2; t++) {
            const int row = t ? r1a : r0a;
            const uint32_t so = (uint32_t)(row * LDE + s0) * 2;
            const size_t ga = (size_t)(rowBase + row) * Fq + kt + s0;
            const size_t gb = (size_t)(colBase + row) * Fq + kt + s0;
            cpasync16(sb + so,              Xh + ga);
            cpasync16(sb + TILE_B + so,     Xl + ga);
            cpasync16(sb + 2 * TILE_B + so, Wh + gb);
            cpasync16(sb + 3 * TILE_B + so, Wl + gb);
        }
        asm volatile("cp.async.commit_group;");
    };

    const int lj = lane >> 3, lr = lane & 7;
    const int arow = (lj & 1) * 8 + lr;
    const int acol = (lj >> 1) * 8;
    const int brow = (lj >> 1) * 8 + lr;
    const int bcol = (lj & 1) * 8;

    stage(0, 0);

    const int NCHUNK = Fq / KC;               // 16
    for (int c = 0; c < NCHUNK; c++) {
        if (c + 1 < NCHUNK) stage((c + 1) & 1, (c + 1) * KC);
        if (c + 1 < NCHUNK) asm volatile("cp.async.wait_group 1;");
        else                asm volatile("cp.async.wait_group 0;");
        __syncthreads();

        const uint32_t sb = sbase + (c & 1) * BUF_B;
#pragma unroll
        for (int ks = 0; ks < 2; ks++) {
            const int kof = ks * 16;
            uint32_t ah[4][4], bh[2][4], bl[2][4], al[4][4];
#pragma unroll
            for (int mt = 0; mt < 4; mt++)
                ldsm_x4(ah[mt][0], ah[mt][1], ah[mt][2], ah[mt][3],
                        sb + (uint32_t)((wm + mt * 16 + arow) * LDE + kof + acol) * 2);
#pragma unroll
            for (int np = 0; np < 2; np++)
                ldsm_x4(bh[np][0], bh[np][1], bh[np][2], bh[np][3],
                        sb + 2 * TILE_B + (uint32_t)((wn + np * 16 + brow) * LDE + kof + bcol) * 2);
#pragma unroll
            for (int mt = 0; mt < 4; mt++)
#pragma unroll
                for (int nt = 0; nt < 4; nt++)
                    mma_bf16(acc[mt][nt], ah[mt],
                             bh[nt >> 1][(nt & 1) * 2], bh[nt >> 1][(nt & 1) * 2 + 1]);
#pragma unroll
            for (int np = 0; np < 2; np++)
                ldsm_x4(bl[np][0], bl[np][1], bl[np][2], bl[np][3],
                        sb + 3 * TILE_B + (uint32_t)((wn + np * 16 + brow) * LDE + kof + bcol) * 2);
#pragma unroll
            for (int mt = 0; mt < 4; mt++)
#pragma unroll
                for (int nt = 0; nt < 4; nt++)
                    mma_bf16(acc[mt][nt], ah[mt],
                             bl[nt >> 1][(nt & 1) * 2], bl[nt >> 1][(nt & 1) * 2 + 1]);
#pragma unroll
            for (int mt = 0; mt < 4; mt++)
                ldsm_x4(al[mt][0], al[mt][1], al[mt][2], al[mt][3],
                        sb + TILE_B + (uint32_t)((wm + mt * 16 + arow) * LDE + kof + acol) * 2);
#pragma unroll
            for (int mt = 0; mt < 4; mt++)
#pragma unroll
                for (int nt = 0; nt < 4; nt++)
                    mma_bf16(acc[mt][nt], al[mt],
                             bh[nt >> 1][(nt & 1) * 2], bh[nt >> 1][(nt & 1) * 2 + 1]);
        }
        __syncthreads();
    }

    // epilogue: thread t of m16n8 tile: rows g, g+8 (g=t/4), cols 2*(t%4)
    const int g = lane >> 2, tg = lane & 3;
    if (z == 0) {
#pragma unroll
        for (int mt = 0; mt < 4; mt++)
#pragma unroll
            for (int nt = 0; nt < 4; nt++) {
                const int row = rowBase + wm + mt * 16 + g;
                const int col = colBase + wn + nt * 8 + 2 * tg;
                *(float2*)(g_Q + (size_t)row * Eq + col) =
                    make_float2(acc[mt][nt][0], acc[mt][nt][1]);
                *(float2*)(g_Q + (size_t)(row + 8) * Eq + col) =
                    make_float2(acc[mt][nt][2], acc[mt][nt][3]);
            }
    } else {
#pragma unroll
        for (int mt = 0; mt < 4; mt++)
#pragma unroll
            for (int nt = 0; nt < 4; nt++) {
                const int row = rowBase + wm + mt * 16 + g;
                const int col = colBase + wn + nt * 8 + 2 * tg;
                *(__half2*)(g_Kh + (size_t)row * Eq + col) =
                    __floats2half2_rn(acc[mt][nt][0], acc[mt][nt][1]);
                *(__half2*)(g_Kh + (size_t)(row + 8) * Eq + col) =
                    __floats2half2_rn(acc[mt][nt][2], acc[mt][nt][3]);
            }
    }
}

// ---------------------------------------------------------------------------
// Fused epilogue: one CTA (256 thr, 8 warps) per token (b,n).
// K gathered as fp16 rows (1KB): lane l reads one uint4 (8 halves) per
// 256-element chunk c; element e = c*256 + l*8 + j -> head 4c + (l>>3);
// reduce over 8-lane groups (shfl_xor 1,2,4).
// proj keeps fp32 Q path (chunked c*128+l*4, 16-lane reduce).
// ---------------------------------------------------------------------------
__device__ __forceinline__ float red16(float s) {
    s += __shfl_xor_sync(0xffffffffu, s, 1);
    s += __shfl_xor_sync(0xffffffffu, s, 2);
    s += __shfl_xor_sync(0xffffffffu, s, 4);
    s += __shfl_xor_sync(0xffffffffu, s, 8);
    return s;
}
__device__ __forceinline__ float red8(float s) {
    s += __shfl_xor_sync(0xffffffffu, s, 1);
    s += __shfl_xor_sync(0xffffffffu, s, 2);
    s += __shfl_xor_sync(0xffffffffu, s, 4);
    return s;
}

__global__ __launch_bounds__(256, 4) void fuse_kernel(
    const float* __restrict__ pl,     // (B,N,M,P)
    const int*   __restrict__ nbhd,   // (B,N,M)
    const float* __restrict__ Wl,     // (P,E)
    const float* __restrict__ u,      // 512 contiguous
    const float* __restrict__ v,      // 512 contiguous
    float*       __restrict__ out)    // (B,N,M,H)
{
    const int bn = blockIdx.x;        // 0..4095
    const int b  = bn >> 11;

    __shared__ float proj[Pq][Hq];
    __shared__ float kb[Hq];
    __shared__ float cont[Mq][Hq];

    const int tid = threadIdx.x;
    const int w = tid >> 5;
    const int l = tid & 31;

    if (w < 6) {
        // proj[w][h] = sum_d Wl[w,:] * (Q + v), fp32 Q, old chunked mapping
        const float* Qg = g_Q + (size_t)bn * Eq;
        const float* wlr = Wl + w * Eq;
        const int hsub = l >> 4;
#pragma unroll
        for (int c = 0; c < 4; c++) {
            float4 qc = *(const float4*)(Qg + c * 128 + l * 4);
            float4 wv = *(const float4*)(wlr + c * 128 + l * 4);
            float4 vf = *(const float4*)(v + c * 128 + l * 4);
            float s = 0.f;
            s = fmaf(wv.x, qc.x + vf.x, s);
            s = fmaf(wv.y, qc.y + vf.y, s);
            s = fmaf(wv.z, qc.z + vf.z, s);
            s = fmaf(wv.w, qc.w + vf.w, s);
            s = red16(s);
            if ((l & 15) == 0) proj[w][2 * c + hsub] = s;
        }
    } else if (w == 6) {
        // kb[h] = sum_d K*u, fp16 K, new chunked mapping
        const __half* Kg = g_Kh + (size_t)bn * Eq;
#pragma unroll
        for (int c = 0; c < 2; c++) {
            uint4 kv = *(const uint4*)(Kg + c * 256 + l * 8);
            float kf[8];
            h8_to_f(kv, kf);
            float4 u0 = *(const float4*)(u + c * 256 + l * 8);
            float4 u1 = *(const float4*)(u + c * 256 + l * 8 + 4);
            float s = 0.f;
            s = fmaf(kf[0], u0.x, s); s = fmaf(kf[1], u0.y, s);
            s = fmaf(kf[2], u0.z, s); s = fmaf(kf[3], u0.w, s);
            s = fmaf(kf[4], u1.x, s); s = fmaf(kf[5], u1.y, s);
            s = fmaf(kf[6], u1.z, s); s = fmaf(kf[7], u1.w, s);
            s = red8(s);
            if ((l & 7) == 0) kb[c * 4 + (l >> 3)] = s;
        }
    }

    // ---- content: all 8 warps, 4 m each, 2 rows in flight ----
    // Q slice (fp32) matching the fp16 chunk mapping
    float q16[16];
#pragma unroll
    for (int c = 0; c < 2; c++) {
        float4 a = *(const float4*)(g_Q + (size_t)bn * Eq + c * 256 + l * 8);
        float4 bb = *(const float4*)(g_Q + (size_t)bn * Eq + c * 256 + l * 8 + 4);
        q16[c * 8 + 0] = a.x;  q16[c * 8 + 1] = a.y;
        q16[c * 8 + 2] = a.z;  q16[c * 8 + 3] = a.w;
        q16[c * 8 + 4] = bb.x; q16[c * 8 + 5] = bb.y;
        q16[c * 8 + 6] = bb.z; q16[c * 8 + 7] = bb.w;
    }

    const __half* Kbase = g_Kh + (size_t)b * Nq * Eq;
    const int* nbp = nbhd + (size_t)bn * Mq;
#pragma unroll
    for (int mi = 0; mi < 4; mi += 2) {
        const int m0 = w + mi * 8;
        const int m1 = w + (mi + 1) * 8;
        const __half* Kp0 = Kbase + (size_t)nbp[m0] * Eq;
        const __half* Kp1 = Kbase + (size_t)nbp[m1] * Eq;
        uint4 k0c0 = *(const uint4*)(Kp0 + l * 8);
        uint4 k0c1 = *(const uint4*)(Kp0 + 256 + l * 8);
        uint4 k1c0 = *(const uint4*)(Kp1 + l * 8);
        uint4 k1c1 = *(const uint4*)(Kp1 + 256 + l * 8);

#pragma unroll
        for (int c = 0; c < 2; c++) {
            float k0f[8], k1f[8];
            h8_to_f(c ? k0c1 : k0c0, k0f);
            h8_to_f(c ? k1c1 : k1c0, k1f);
            float s0 = 0.f, s1 = 0.f;
#pragma unroll
            for (int j = 0; j < 8; j++) {
                s0 = fmaf(k0f[j], q16[c * 8 + j], s0);
                s1 = fmaf(k1f[j], q16[c * 8 + j], s1);
            }
            s0 = red8(s0);
            s1 = red8(s1);
            if ((l & 7) == 0) {
                cont[m0][c * 4 + (l >> 3)] = s0;
                cont[m1][c * 4 + (l >> 3)] = s1;
            }
        }
    }
    __syncthreads();

    // combine: thread t -> (m, h)
    const int m = tid >> 3;
    const int h = tid & 7;
    const float* plp = pl + ((size_t)bn * Mq + m) * Pq;
    float p = 0.f;
#pragma unroll
    for (int pp = 0; pp < Pq; pp++) p = fmaf(plp[pp], proj[pp][h], p);
    out[((size_t)bn * Mq + m) * Hq + h] = (cont[m][h] + p + kb[h]) * 0.125f;
}

// ---------------------------------------------------------------------------
// Launch
// Inputs: 0 pairwise_locations, 1 mask (unused), 2 query_features,
// 3 key_features, 4 nbhd_idx, 5 Wq, 6 Wk, 7 Wl, 8 u, 9 v
// ---------------------------------------------------------------------------
extern "C" void kernel_launch(void* const* d_in, const int* in_sizes, int n_in,
                              void* d_out, int out_size)
{
    const float* pl   = (const float*)d_in[0];
    const float* qf   = (const float*)d_in[2];
    const float* kf   = (const float*)d_in[3];
    const int*   nb   = (const int*)  d_in[4];
    const float* Wq_  = (const float*)d_in[5];
    const float* Wk_  = (const float*)d_in[6];
    const float* Wl   = (const float*)d_in[7];
    const float* u    = (const float*)d_in[8];
    const float* v    = (const float*)d_in[9];
    float*       out  = (float*)d_out;

    static int smem_set = 0;
    if (!smem_set) {
        cudaFuncSetAttribute(gemm_tc_kernel,
                             cudaFuncAttributeMaxDynamicSharedMemorySize, GEMM_SMEM);
        smem_set = 1;
    }

    prep_kernel<<<dim3(2304, 1, 2), 256>>>(qf, kf, Wq_, Wk_);
    gemm_tc_kernel<<<dim3(4, 32, 2), 256, GEMM_SMEM>>>();
    fuse_kernel<<<Bq * Nq, 256>>>(pl, nb, Wl, u, v, out);
}

// round 6
// speedup vs baseline: 3.7705x; 1.4425x over previous
#include <cuda_runtime.h>
#include <cuda_fp16.h>
#include <cstdint>

// Shapes (fixed by the problem)
#define Bq 2
#define Nq 2048
#define Mq 32
#define Hq 8
#define Dq 64
#define Eq 512
#define Fq 512
#define Pq 6

// ---------------------------------------------------------------------------
// Scratch (graph-capture rules forbid cudaMalloc)
// ---------------------------------------------------------------------------
__device__ float  g_Q [Bq * Nq * Eq];     // fp32 Q projections (proj path + content Q)
__device__ __half g_Kh[Bq * Nq * Eq];     // fp16 K projections (gather + kb)
__device__ __half g_x16[2][Bq * Nq * Fq]; // fp16 inputs: [0]=qf, [1]=kf
__device__ __half g_w16[2][Eq * Fq];      // fp16 transposed weights [n][k]: [0]=Wq, [1]=Wk

// ---------------------------------------------------------------------------
// helpers
// ---------------------------------------------------------------------------
__device__ __forceinline__ uint32_t smem_u32(const void* p) {
    uint32_t a;
    asm("{ .reg .u64 t; cvta.to.shared.u64 t, %1; cvt.u32.u64 %0, t; }" : "=r"(a) : "l"(p));
    return a;
}
__device__ __forceinline__ void cpasync16(uint32_t s, const void* g) {
    asm volatile("cp.async.cg.shared.global [%0], [%1], 16;" :: "r"(s), "l"(g));
}
__device__ __forceinline__ void ldsm_x4(uint32_t& r0, uint32_t& r1, uint32_t& r2, uint32_t& r3,
                                        uint32_t addr) {
    asm volatile("ldmatrix.sync.aligned.m8n8.x4.shared.b16 {%0,%1,%2,%3}, [%4];"
                 : "=r"(r0), "=r"(r1), "=r"(r2), "=r"(r3) : "r"(addr));
}
__device__ __forceinline__ void mma_f16(float* c, const uint32_t* a, uint32_t b0, uint32_t b1) {
    asm volatile(
        "mma.sync.aligned.m16n8k16.row.col.f32.f16.f16.f32 "
        "{%0,%1,%2,%3}, {%4,%5,%6,%7}, {%8,%9}, {%0,%1,%2,%3};"
        : "+f"(c[0]), "+f"(c[1]), "+f"(c[2]), "+f"(c[3])
        : "r"(a[0]), "r"(a[1]), "r"(a[2]), "r"(a[3]), "r"(b0), "r"(b1));
}
// 8 packed halves (one uint4) -> 8 floats
__device__ __forceinline__ void h8_to_f(const uint4& kv, float* f) {
    const __half2* hp = reinterpret_cast<const __half2*>(&kv);
#pragma unroll
    for (int i = 0; i < 4; i++) {
        float2 t = __half22float2(hp[i]);
        f[2 * i] = t.x;
        f[2 * i + 1] = t.y;
    }
}

// ---------------------------------------------------------------------------
// prep: blocks 0..2047 convert X fp32->fp16; blocks 2048..2303 transpose+convert W.
// z = 0 -> (qf, Wq); z = 1 -> (kf, Wk).
// ---------------------------------------------------------------------------
__global__ __launch_bounds__(256) void prep_kernel(
    const float* __restrict__ qf, const float* __restrict__ kf,
    const float* __restrict__ Wq_, const float* __restrict__ Wk_)
{
    __shared__ float tile[32][33];
    const int z = blockIdx.z;
    const int tid = threadIdx.x;

    if (blockIdx.x < 2048) {
        const int f4 = blockIdx.x * 256 + tid;          // 0..524287 (x4 floats)
        const float* in = z ? kf : qf;
        __half* o = g_x16[z];
        float4 x = ((const float4*)in)[f4];
        __half2 h0 = __floats2half2_rn(x.x, x.y);
        __half2 h1 = __floats2half2_rn(x.z, x.w);
        ((uint2*)o)[f4] = make_uint2(*(uint32_t*)&h0, *(uint32_t*)&h1);
    } else {
        const int bx = blockIdx.x - 2048;               // 0..255
        const float* in = z ? Wk_ : Wq_;
        __half* o = g_w16[z];
        const int tx = tid & 31, ty = tid >> 5;         // 32 x 8
        const int n0 = (bx & 15) * 32, k0 = (bx >> 4) * 32;
#pragma unroll
        for (int j = 0; j < 4; j++)
            tile[ty + j * 8][tx] = in[(size_t)(k0 + ty + j * 8) * Eq + n0 + tx];
        __syncthreads();
#pragma unroll
        for (int j = 0; j < 4; j++)
            o[(size_t)(n0 + ty + j * 8) * Fq + k0 + tx] = __float2half_rn(tile[tx][ty + j * 8]);
    }
}

// ---------------------------------------------------------------------------
// GEMM via single-pass fp16 mma.sync: C[4096,512] = X @ W.
// CTA tile 128x128, 8 warps (2x4), warp tile 64x32 (4x4 m16n8k16).
// K-chunk 32, double-buffered cp.async. grid (4, 32, 2), 256 thr.
// z=0 writes fp32 g_Q; z=1 writes fp16 g_Kh.
// ---------------------------------------------------------------------------
#define KC 32
#define LDE 40                       // elements per smem row (80B: LDSM conflict-free)
#define TILE_B (128 * LDE * 2)       // 10240 bytes per tile
#define BUF_B (2 * TILE_B)           // A, B
#define GEMM_SMEM (2 * BUF_B)        // 40960

__global__ __launch_bounds__(256, 2) void gemm_tc_kernel()
{
    extern __shared__ char smem[];
    const uint32_t sbase = smem_u32(smem);
    const int tid = threadIdx.x;
    const int wid = tid >> 5;
    const int lane = tid & 31;
    const int z = blockIdx.z;
    const int rowBase = blockIdx.y * 128;
    const int colBase = blockIdx.x * 128;

    const __half* X = g_x16[z];
    const __half* W = g_w16[z];

    const int wm = (wid >> 2) * 64;
    const int wn = (wid & 3) * 32;

    const int r0a = tid >> 2, s0 = (tid & 3) * 8;
    const int r1a = (tid + 256) >> 2;

    float acc[4][4][4];
#pragma unroll
    for (int mt = 0; mt < 4; mt++)
#pragma unroll
        for (int nt = 0; nt < 4; nt++)
#pragma unroll
            for (int i = 0; i < 4; i++) acc[mt][nt][i] = 0.f;

    auto stage = [&](int buf, int kt) {
        const uint32_t sb = sbase + buf * BUF_B;
#pragma unroll
        for (int t = 0; t < 2; t++) {
            const int row = t ? r1a : r0a;
            const uint32_t so = (uint32_t)(row * LDE + s0) * 2;
            cpasync16(sb + so,          X + (size_t)(rowBase + row) * Fq + kt + s0);
            cpasync16(sb + TILE_B + so, W + (size_t)(colBase + row) * Fq + kt + s0);
        }
        asm volatile("cp.async.commit_group;");
    };

    const int lj = lane >> 3, lr = lane & 7;
    const int arow = (lj & 1) * 8 + lr;
    const int acol = (lj >> 1) * 8;
    const int brow = (lj >> 1) * 8 + lr;
    const int bcol = (lj & 1) * 8;

    stage(0, 0);

    const int NCHUNK = Fq / KC;               // 16
    for (int c = 0; c < NCHUNK; c++) {
        if (c + 1 < NCHUNK) stage((c + 1) & 1, (c + 1) * KC);
        if (c + 1 < NCHUNK) asm volatile("cp.async.wait_group 1;");
        else                asm volatile("cp.async.wait_group 0;");
        __syncthreads();

        const uint32_t sb = sbase + (c & 1) * BUF_B;
#pragma unroll
        for (int ks = 0; ks < 2; ks++) {
            const int kof = ks * 16;
            uint32_t a[4][4], bfr[2][4];
#pragma unroll
            for (int mt = 0; mt < 4; mt++)
                ldsm_x4(a[mt][0], a[mt][1], a[mt][2], a[mt][3],
                        sb + (uint32_t)((wm + mt * 16 + arow) * LDE + kof + acol) * 2);
#pragma unroll
            for (int np = 0; np < 2; np++)
                ldsm_x4(bfr[np][0], bfr[np][1], bfr[np][2], bfr[np][3],
                        sb + TILE_B + (uint32_t)((wn + np * 16 + brow) * LDE + kof + bcol) * 2);
#pragma unroll
            for (int mt = 0; mt < 4; mt++)
#pragma unroll
                for (int nt = 0; nt < 4; nt++)
                    mma_f16(acc[mt][nt], a[mt],
                            bfr[nt >> 1][(nt & 1) * 2], bfr[nt >> 1][(nt & 1) * 2 + 1]);
        }
        __syncthreads();
    }

    // epilogue: thread t of m16n8 tile: rows g, g+8 (g=t/4), cols 2*(t%4)
    const int g = lane >> 2, tg = lane & 3;
    if (z == 0) {
#pragma unroll
        for (int mt = 0; mt < 4; mt++)
#pragma unroll
            for (int nt = 0; nt < 4; nt++) {
                const int row = rowBase + wm + mt * 16 + g;
                const int col = colBase + wn + nt * 8 + 2 * tg;
                *(float2*)(g_Q + (size_t)row * Eq + col) =
                    make_float2(acc[mt][nt][0], acc[mt][nt][1]);
                *(float2*)(g_Q + (size_t)(row + 8) * Eq + col) =
                    make_float2(acc[mt][nt][2], acc[mt][nt][3]);
            }
    } else {
#pragma unroll
        for (int mt = 0; mt < 4; mt++)
#pragma unroll
            for (int nt = 0; nt < 4; nt++) {
                const int row = rowBase + wm + mt * 16 + g;
                const int col = colBase + wn + nt * 8 + 2 * tg;
                *(__half2*)(g_Kh + (size_t)row * Eq + col) =
                    __floats2half2_rn(acc[mt][nt][0], acc[mt][nt][1]);
                *(__half2*)(g_Kh + (size_t)(row + 8) * Eq + col) =
                    __floats2half2_rn(acc[mt][nt][2], acc[mt][nt][3]);
            }
    }
}

// ---------------------------------------------------------------------------
// Fused epilogue: one CTA (256 thr, 8 warps) per token (b,n).
// K gathered as fp16 rows (1KB). Element e = c*256 + l*8 + j -> head 4c + (l>>3);
// reduce over 8-lane groups. All 8 gather LDG.128s issued before any compute.
// ---------------------------------------------------------------------------
__device__ __forceinline__ float red16(float s) {
    s += __shfl_xor_sync(0xffffffffu, s, 1);
    s += __shfl_xor_sync(0xffffffffu, s, 2);
    s += __shfl_xor_sync(0xffffffffu, s, 4);
    s += __shfl_xor_sync(0xffffffffu, s, 8);
    return s;
}
__device__ __forceinline__ float red8(float s) {
    s += __shfl_xor_sync(0xffffffffu, s, 1);
    s += __shfl_xor_sync(0xffffffffu, s, 2);
    s += __shfl_xor_sync(0xffffffffu, s, 4);
    return s;
}

__global__ __launch_bounds__(256, 3) void fuse_kernel(
    const float* __restrict__ pl,     // (B,N,M,P)
    const int*   __restrict__ nbhd,   // (B,N,M)
    const float* __restrict__ Wl,     // (P,E)
    const float* __restrict__ u,      // 512 contiguous
    const float* __restrict__ v,      // 512 contiguous
    float*       __restrict__ out)    // (B,N,M,H)
{
    const int bn = blockIdx.x;        // 0..4095
    const int b  = bn >> 11;

    __shared__ float proj[Pq][Hq];
    __shared__ float kb[Hq];
    __shared__ float cont[Mq][Hq];

    const int tid = threadIdx.x;
    const int w = tid >> 5;
    const int l = tid & 31;

    // ---- issue all gather loads first (max MLP) ----
    const __half* Kbase = g_Kh + (size_t)b * Nq * Eq;
    const int* nbp = nbhd + (size_t)bn * Mq;
    int mrow[4];
    uint4 kv[4][2];
#pragma unroll
    for (int mi = 0; mi < 4; mi++) {
        mrow[mi] = w + mi * 8;
        const __half* Kp = Kbase + (size_t)nbp[mrow[mi]] * Eq;
        kv[mi][0] = *(const uint4*)(Kp + l * 8);
        kv[mi][1] = *(const uint4*)(Kp + 256 + l * 8);
    }

    // Q slice (fp32) matching the fp16 chunk mapping
    float q16[16];
#pragma unroll
    for (int c = 0; c < 2; c++) {
        float4 a = *(const float4*)(g_Q + (size_t)bn * Eq + c * 256 + l * 8);
        float4 bb = *(const float4*)(g_Q + (size_t)bn * Eq + c * 256 + l * 8 + 4);
        q16[c * 8 + 0] = a.x;  q16[c * 8 + 1] = a.y;
        q16[c * 8 + 2] = a.z;  q16[c * 8 + 3] = a.w;
        q16[c * 8 + 4] = bb.x; q16[c * 8 + 5] = bb.y;
        q16[c * 8 + 6] = bb.z; q16[c * 8 + 7] = bb.w;
    }

    if (w < 6) {
        // proj[w][h] = sum_d Wl[w,:] * (Q + v): fp32 Q, chunked c*128+l*4 map
        const float* Qg = g_Q + (size_t)bn * Eq;
        const float* wlr = Wl + w * Eq;
        const int hsub = l >> 4;
#pragma unroll
        for (int c = 0; c < 4; c++) {
            float4 qc = *(const float4*)(Qg + c * 128 + l * 4);
            float4 wv = *(const float4*)(wlr + c * 128 + l * 4);
            float4 vf = *(const float4*)(v + c * 128 + l * 4);
            float s = 0.f;
            s = fmaf(wv.x, qc.x + vf.x, s);
            s = fmaf(wv.y, qc.y + vf.y, s);
            s = fmaf(wv.z, qc.z + vf.z, s);
            s = fmaf(wv.w, qc.w + vf.w, s);
            s = red16(s);
            if ((l & 15) == 0) proj[w][2 * c + hsub] = s;
        }
    } else if (w == 6) {
        // kb[h] = sum_d K*u (fp16 K, own row)
        const __half* Kg = g_Kh + (size_t)bn * Eq;
#pragma unroll
        for (int c = 0; c < 2; c++) {
            uint4 kk = *(const uint4*)(Kg + c * 256 + l * 8);
            float kf[8];
            h8_to_f(kk, kf);
            float4 u0 = *(const float4*)(u + c * 256 + l * 8);
            float4 u1 = *(const float4*)(u + c * 256 + l * 8 + 4);
            float s = 0.f;
            s = fmaf(kf[0], u0.x, s); s = fmaf(kf[1], u0.y, s);
            s = fmaf(kf[2], u0.z, s); s = fmaf(kf[3], u0.w, s);
            s = fmaf(kf[4], u1.x, s); s = fmaf(kf[5], u1.y, s);
            s = fmaf(kf[6], u1.z, s); s = fmaf(kf[7], u1.w, s);
            s = red8(s);
            if ((l & 7) == 0) kb[c * 4 + (l >> 3)] = s;
        }
    }

    // ---- content reductions ----
#pragma unroll
    for (int mi = 0; mi < 4; mi++) {
#pragma unroll
        for (int c = 0; c < 2; c++) {
            float kf[8];
            h8_to_f(kv[mi][c], kf);
            float s = 0.f;
#pragma unroll
            for (int j = 0; j < 8; j++) s = fmaf(kf[j], q16[c * 8 + j], s);
            s = red8(s);
            if ((l & 7) == 0) cont[mrow[mi]][c * 4 + (l >> 3)] = s;
        }
    }
    __syncthreads();

    // combine: thread t -> (m, h)
    const int m = tid >> 3;
    const int h = tid & 7;
    const float* plp = pl + ((size_t)bn * Mq + m) * Pq;
    float p = 0.f;
#pragma unroll
    for (int pp = 0; pp < Pq; pp++) p = fmaf(plp[pp], proj[pp][h], p);
    out[((size_t)bn * Mq + m) * Hq + h] = (cont[m][h] + p + kb[h]) * 0.125f;
}

// ---------------------------------------------------------------------------
// Launch
// Inputs: 0 pairwise_locations, 1 mask (unused), 2 query_features,
// 3 key_features, 4 nbhd_idx, 5 Wq, 6 Wk, 7 Wl, 8 u, 9 v
// ---------------------------------------------------------------------------
extern "C" void kernel_launch(void* const* d_in, const int* in_sizes, int n_in,
                              void* d_out, int out_size)
{
    const float* pl   = (const float*)d_in[0];
    const float* qf   = (const float*)d_in[2];
    const float* kf   = (const float*)d_in[3];
    const int*   nb   = (const int*)  d_in[4];
    const float* Wq_  = (const float*)d_in[5];
    const float* Wk_  = (const float*)d_in[6];
    const float* Wl   = (const float*)d_in[7];
    const float* u    = (const float*)d_in[8];
    const float* v    = (const float*)d_in[9];
    float*       out  = (float*)d_out;

    static int smem_set = 0;
    if (!smem_set) {
        cudaFuncSetAttribute(gemm_tc_kernel,
                             cudaFuncAttributeMaxDynamicSharedMemorySize, GEMM_SMEM);
        smem_set = 1;
    }

    prep_kernel<<<dim3(2304, 1, 2), 256>>>(qf, kf, Wq_, Wk_);
    gemm_tc_kernel<<<dim3(4, 32, 2), 256, GEMM_SMEM>>>();
    fuse_kernel<<<Bq * Nq, 256>>>(pl, nb, Wl, u, v, out);
}